// round 1
// baseline (speedup 1.0000x reference)
#include <cuda_runtime.h>
#include <math.h>

// ---------------- problem constants ----------------
#define NMAX 100000
#define EMAX 800000
#define NC 416            // packed GEMM output cols: Q(128) K(128) V(128) S(32)
#define QS_STRIDE 160     // q(128) + skip(32)
#define KV_STRIDE 256     // k(128) + v(128)
#define SCAN_B 1024

// ---------------- scratch (device globals; no allocs allowed) ----------------
__device__ float g_qs[(size_t)NMAX * QS_STRIDE];
__device__ float g_kv[(size_t)NMAX * KV_STRIDE];
__device__ float g_h[(size_t)NMAX * 32];
__device__ float g_Wcat[128 * NC];
__device__ float g_bcat[NC];
__device__ int   g_cnt[NMAX];
__device__ int   g_rowptr[NMAX + 1];
__device__ int   g_cursor[NMAX];
__device__ int   g_eid[EMAX];
__device__ int   g_bsums[1024];

// ---------------- CSR build ----------------
__global__ void k_zero_cnt(int n) {
    int i = blockIdx.x * blockDim.x + threadIdx.x;
    if (i < n) g_cnt[i] = 0;
}

__global__ void k_hist(const int* __restrict__ dst, int e) {
    int i = blockIdx.x * blockDim.x + threadIdx.x;
    if (i < e) atomicAdd(&g_cnt[dst[i]], 1);
}

__global__ void k_scan1(int n) {
    __shared__ int sm[SCAN_B];
    int i = blockIdx.x * SCAN_B + threadIdx.x;
    int v = (i < n) ? g_cnt[i] : 0;
    sm[threadIdx.x] = v;
    for (int off = 1; off < SCAN_B; off <<= 1) {
        __syncthreads();
        int t = (threadIdx.x >= off) ? sm[threadIdx.x - off] : 0;
        __syncthreads();
        sm[threadIdx.x] += t;
    }
    __syncthreads();
    if (i < n) g_rowptr[i + 1] = sm[threadIdx.x];
    if (threadIdx.x == SCAN_B - 1) g_bsums[blockIdx.x] = sm[SCAN_B - 1];
}

__global__ void k_scan2(int nb) {
    __shared__ int sm[SCAN_B];
    int v = (threadIdx.x < nb) ? g_bsums[threadIdx.x] : 0;
    sm[threadIdx.x] = v;
    for (int off = 1; off < SCAN_B; off <<= 1) {
        __syncthreads();
        int t = (threadIdx.x >= off) ? sm[threadIdx.x - off] : 0;
        __syncthreads();
        sm[threadIdx.x] += t;
    }
    __syncthreads();
    if (threadIdx.x < nb) g_bsums[threadIdx.x] = sm[threadIdx.x] - v; // exclusive
}

__global__ void k_scan3(int n) {
    int i = blockIdx.x * SCAN_B + threadIdx.x;
    if (i < n) g_rowptr[i + 1] += g_bsums[blockIdx.x];
    if (i == 0) g_rowptr[0] = 0;
}

__global__ void k_cursor(int n) {
    int i = blockIdx.x * blockDim.x + threadIdx.x;
    if (i < n) g_cursor[i] = g_rowptr[i];
}

__global__ void k_scatter(const int* __restrict__ dst, int e) {
    int i = blockIdx.x * blockDim.x + threadIdx.x;
    if (i < e) {
        int p = atomicAdd(&g_cursor[dst[i]], 1);
        g_eid[p] = i;
    }
}

// ---------------- weight packing: Wcat[K][416], bcat[416] ----------------
__global__ void k_pack(const float* __restrict__ Wq, const float* __restrict__ bq,
                       const float* __restrict__ Wk, const float* __restrict__ bk,
                       const float* __restrict__ Wv, const float* __restrict__ bv,
                       const float* __restrict__ Ws, const float* __restrict__ bs,
                       int K) {
    int i = blockIdx.x * blockDim.x + threadIdx.x;
    if (i < K * NC) {
        int k = i / NC, j = i % NC;
        float w;
        if (j < 128)      w = Wq[k * 128 + j];
        else if (j < 256) w = Wk[k * 128 + (j - 128)];
        else if (j < 384) w = Wv[k * 128 + (j - 256)];
        else              w = Ws[k * 32 + (j - 384)];
        g_Wcat[k * NC + j] = w;
    }
    if (i < NC) {
        float b;
        if (i < 128)      b = bq[i];
        else if (i < 256) b = bk[i - 128];
        else if (i < 384) b = bv[i - 256];
        else              b = bs[i - 384];
        g_bcat[i] = b;
    }
}

// ---------------- fused QKV+skip GEMM: C[M,416] = A[M,K] @ Wcat + bcat ----------------
// BM=128, BN=64, BK=32, 256 threads, 8x4 micro-tile per thread.
// useH != 0 -> A = g_h (layer-1 input), else A = external x pointer.
__global__ void __launch_bounds__(256) k_gemm(const float* __restrict__ A_ext, int useH, int M, int K) {
    __shared__ float As[128 * 36];
    __shared__ float Bs[32 * 68];
    const float* __restrict__ A = useH ? g_h : A_ext;
    int m0 = blockIdx.x * 128;
    int n0 = blockIdx.y * 64;
    int tid = threadIdx.x;
    int ty = tid >> 4, tx = tid & 15;

    float acc[8][4];
#pragma unroll
    for (int i = 0; i < 8; ++i)
#pragma unroll
        for (int j = 0; j < 4; ++j) acc[i][j] = 0.f;

    for (int k0 = 0; k0 < K; k0 += 32) {
#pragma unroll
        for (int t = 0; t < 4; ++t) {
            int idx = tid + t * 256;          // 0..1023 covers 128x32
            int r = idx >> 3;
            int c = (idx & 7) << 2;
            float4 v = make_float4(0.f, 0.f, 0.f, 0.f);
            int grow = m0 + r;
            if (grow < M) v = *(const float4*)(A + (size_t)grow * K + (k0 + c));
            *(float4*)&As[r * 36 + c] = v;
        }
#pragma unroll
        for (int t = 0; t < 2; ++t) {
            int idx = tid + t * 256;          // 0..511 covers 32x64
            int r = idx >> 4;
            int c = (idx & 15) << 2;
            float4 v = make_float4(0.f, 0.f, 0.f, 0.f);
            int gcol = n0 + c;
            if (gcol < NC) v = *(const float4*)(g_Wcat + (size_t)(k0 + r) * NC + gcol);
            *(float4*)&Bs[r * 68 + c] = v;
        }
        __syncthreads();
#pragma unroll 8
        for (int kk = 0; kk < 32; ++kk) {
            float4 b4 = *(const float4*)&Bs[kk * 68 + tx * 4];
#pragma unroll
            for (int i = 0; i < 8; ++i) {
                float a = As[(ty * 8 + i) * 36 + kk];
                acc[i][0] += a * b4.x;
                acc[i][1] += a * b4.y;
                acc[i][2] += a * b4.z;
                acc[i][3] += a * b4.w;
            }
        }
        __syncthreads();
    }

#pragma unroll
    for (int i = 0; i < 8; ++i) {
        int row = m0 + ty * 8 + i;
        if (row >= M) continue;
#pragma unroll
        for (int j = 0; j < 4; ++j) {
            int col = n0 + tx * 4 + j;
            if (col >= NC) continue;
            float val = acc[i][j] + g_bcat[col];
            if (col < 128)       g_qs[(size_t)row * QS_STRIDE + col] = val;
            else if (col < 384)  g_kv[(size_t)row * KV_STRIDE + (col - 128)] = val;
            else                 g_qs[(size_t)row * QS_STRIDE + 128 + (col - 384)] = val;
        }
    }
}

// ---------------- attention: warp per destination node, online softmax ----------------
// lane = g*8 + l: head g in [0,4), each lane owns float4 of channels l*4..l*4+3.
// Writes h[n,32] = relu(mean_heads(softmax-agg) + skip).
__global__ void k_attn(const int* __restrict__ src, int n) {
    int gw = (blockIdx.x * blockDim.x + threadIdx.x) >> 5;
    if (gw >= n) return;
    int lane = threadIdx.x & 31;
    int g = lane >> 3, l = lane & 7;
    int off = g * 32 + l * 4;
    const float scale = 0.17677669529663687f;  // 1/sqrt(32)

    float4 q = *(const float4*)(g_qs + (size_t)gw * QS_STRIDE + off);
    float m = -1e30f, ssum = 0.f;
    float ax = 0.f, ay = 0.f, az = 0.f, aw = 0.f;

    int beg = g_rowptr[gw], end = g_rowptr[gw + 1];
    for (int i = beg; i < end; ++i) {
        int e = g_eid[i];
        int s = src[e];
        const float* kb = g_kv + (size_t)s * KV_STRIDE + off;
        float4 k4 = *(const float4*)kb;
        float4 v4 = *(const float4*)(kb + 128);
        float d = q.x * k4.x + q.y * k4.y + q.z * k4.z + q.w * k4.w;
        d += __shfl_xor_sync(0xffffffffu, d, 1);
        d += __shfl_xor_sync(0xffffffffu, d, 2);
        d += __shfl_xor_sync(0xffffffffu, d, 4);
        float alpha = d * scale;
        if (alpha > m) {
            float sc = __expf(m - alpha);
            ssum = ssum * sc + 1.f;
            ax = ax * sc + v4.x;
            ay = ay * sc + v4.y;
            az = az * sc + v4.z;
            aw = aw * sc + v4.w;
            m = alpha;
        } else {
            float p = __expf(alpha - m);
            ssum += p;
            ax += p * v4.x;
            ay += p * v4.y;
            az += p * v4.z;
            aw += p * v4.w;
        }
    }
    float inv = (ssum > 0.f) ? (1.f / ssum) : 0.f;
    ax *= inv; ay *= inv; az *= inv; aw *= inv;

    // mean over 4 heads: sum across lane groups (xor 8, xor 16), then *0.25
    ax += __shfl_xor_sync(0xffffffffu, ax, 8);
    ay += __shfl_xor_sync(0xffffffffu, ay, 8);
    az += __shfl_xor_sync(0xffffffffu, az, 8);
    aw += __shfl_xor_sync(0xffffffffu, aw, 8);
    ax += __shfl_xor_sync(0xffffffffu, ax, 16);
    ay += __shfl_xor_sync(0xffffffffu, ay, 16);
    az += __shfl_xor_sync(0xffffffffu, az, 16);
    aw += __shfl_xor_sync(0xffffffffu, aw, 16);

    if (lane < 8) {
        float4 sk = *(const float4*)(g_qs + (size_t)gw * QS_STRIDE + 128 + l * 4);
        float4 o;
        o.x = fmaxf(ax * 0.25f + sk.x, 0.f);
        o.y = fmaxf(ay * 0.25f + sk.y, 0.f);
        o.z = fmaxf(az * 0.25f + sk.z, 0.f);
        o.w = fmaxf(aw * 0.25f + sk.w, 0.f);
        *(float4*)(g_h + (size_t)gw * 32 + l * 4) = o;
    }
}

// ---------------- output projection: out[n,16] = h[n,32] @ Wout + bout ----------------
__global__ void __launch_bounds__(256) k_outproj(const float* __restrict__ Wout,
                                                 const float* __restrict__ bout,
                                                 float* __restrict__ out, int n) {
    __shared__ float Hs[128 * 32];
    __shared__ float Ws[512];
    __shared__ float Bs2[16];
    int node0 = blockIdx.x * 128;
    for (int i = threadIdx.x; i < 512; i += 256) Ws[i] = Wout[i];
    if (threadIdx.x < 16) Bs2[threadIdx.x] = bout[threadIdx.x];
    for (int i = threadIdx.x; i < 128 * 32; i += 256) {
        int r = node0 + (i >> 5);
        Hs[i] = (r < n) ? g_h[(size_t)node0 * 32 + i] : 0.f;
    }
    __syncthreads();
#pragma unroll
    for (int t = 0; t < 8; ++t) {
        int oi = threadIdx.x + t * 256;   // 0..2047 = 128 nodes x 16 cols
        int ln = oi >> 4;
        int j = oi & 15;
        int node = node0 + ln;
        if (node >= n) continue;
        float acc = Bs2[j];
#pragma unroll
        for (int k = 0; k < 32; ++k) acc += Hs[ln * 32 + k] * Ws[k * 16 + j];
        out[(size_t)node * 16 + j] = acc;
    }
}

// ---------------- launch ----------------
extern "C" void kernel_launch(void* const* d_in, const int* in_sizes, int n_in,
                              void* d_out, int out_size) {
    const float* x = (const float*)d_in[0];
    const int*   ei = (const int*)d_in[1];
    int n = in_sizes[0] / 128;
    int e = in_sizes[1] / 2;
    const int* srcp = ei;
    const int* dstp = ei + e;

    int nb = (n + 255) / 256;
    int eb = (e + 255) / 256;
    int sblocks = (n + SCAN_B - 1) / SCAN_B;

    // CSR by destination (reused for both layers)
    k_zero_cnt<<<nb, 256>>>(n);
    k_hist<<<eb, 256>>>(dstp, e);
    k_scan1<<<sblocks, SCAN_B>>>(n);
    k_scan2<<<1, SCAN_B>>>(sblocks);
    k_scan3<<<sblocks, SCAN_B>>>(n);
    k_cursor<<<nb, 256>>>(n);
    k_scatter<<<eb, 256>>>(dstp, e);

    dim3 gg((n + 127) / 128, (NC + 63) / 64);
    int attn_blocks = (n + 7) / 8;

    // layer 0
    k_pack<<<(128 * NC + 255) / 256, 256>>>(
        (const float*)d_in[2], (const float*)d_in[3],
        (const float*)d_in[4], (const float*)d_in[5],
        (const float*)d_in[6], (const float*)d_in[7],
        (const float*)d_in[8], (const float*)d_in[9], 128);
    k_gemm<<<gg, 256>>>(x, 0, n, 128);
    k_attn<<<attn_blocks, 256>>>(srcp, n);

    // layer 1
    k_pack<<<(32 * NC + 255) / 256, 256>>>(
        (const float*)d_in[10], (const float*)d_in[11],
        (const float*)d_in[12], (const float*)d_in[13],
        (const float*)d_in[14], (const float*)d_in[15],
        (const float*)d_in[16], (const float*)d_in[17], 32);
    k_gemm<<<gg, 256>>>(nullptr, 1, n, 32);
    k_attn<<<attn_blocks, 256>>>(srcp, n);

    // output projection
    k_outproj<<<(n + 127) / 128, 256>>>(
        (const float*)d_in[18], (const float*)d_in[19], (float*)d_out, n);
}

// round 2
// speedup vs baseline: 1.7611x; 1.7611x over previous
#include <cuda_runtime.h>
#include <math.h>
#include <stdint.h>

// ---------------- problem constants ----------------
#define NMAX 100000
#define EMAX 800000
#define NC 416            // packed GEMM output cols: Q(128) K(128) V(128) S(32)
#define QS_STRIDE 160     // q(128) + skip(32)
#define KV_STRIDE 256     // k(128) + v(128)
#define SCAN_B 1024

// ---------------- scratch (device globals; no allocs allowed) ----------------
__device__ float g_qs[(size_t)NMAX * QS_STRIDE];
__device__ float g_kv[(size_t)NMAX * KV_STRIDE];
__device__ float g_h[(size_t)NMAX * 32];
__device__ float g_Wcat0[128 * NC];
__device__ float g_bcat0[NC];
__device__ float g_Wcat1[32 * NC];
__device__ float g_bcat1[NC];
__device__ int   g_cnt[NMAX];
__device__ int   g_rowptr[NMAX + 1];
__device__ int   g_cursor[NMAX];
__device__ int   g_esrc[EMAX];     // src node id per CSR slot (pre-gathered)
__device__ int   g_bsums[1024];

// ---------------- CSR build ----------------
__global__ void k_zero_cnt(int n) {
    int i = blockIdx.x * blockDim.x + threadIdx.x;
    if (i < n) g_cnt[i] = 0;
}

__global__ void k_hist(const int* __restrict__ dst, int e) {
    int i = blockIdx.x * blockDim.x + threadIdx.x;
    if (i < e) atomicAdd(&g_cnt[dst[i]], 1);
}

__global__ void k_scan1(int n) {
    __shared__ int sm[SCAN_B];
    int i = blockIdx.x * SCAN_B + threadIdx.x;
    int v = (i < n) ? g_cnt[i] : 0;
    sm[threadIdx.x] = v;
    for (int off = 1; off < SCAN_B; off <<= 1) {
        __syncthreads();
        int t = (threadIdx.x >= off) ? sm[threadIdx.x - off] : 0;
        __syncthreads();
        sm[threadIdx.x] += t;
    }
    __syncthreads();
    if (i < n) g_rowptr[i + 1] = sm[threadIdx.x];
    if (threadIdx.x == SCAN_B - 1) g_bsums[blockIdx.x] = sm[SCAN_B - 1];
}

__global__ void k_scan2(int nb) {
    __shared__ int sm[SCAN_B];
    int v = (threadIdx.x < nb) ? g_bsums[threadIdx.x] : 0;
    sm[threadIdx.x] = v;
    for (int off = 1; off < SCAN_B; off <<= 1) {
        __syncthreads();
        int t = (threadIdx.x >= off) ? sm[threadIdx.x - off] : 0;
        __syncthreads();
        sm[threadIdx.x] += t;
    }
    __syncthreads();
    if (threadIdx.x < nb) g_bsums[threadIdx.x] = sm[threadIdx.x] - v; // exclusive
}

// scan3 also derives cursor[i] = rowptr[i+1] - cnt[i] (exclusive start), and rowptr[0]=0.
__global__ void k_scan3(int n) {
    int i = blockIdx.x * SCAN_B + threadIdx.x;
    if (i < n) {
        int v = g_rowptr[i + 1] + g_bsums[blockIdx.x];
        g_rowptr[i + 1] = v;
        g_cursor[i] = v - g_cnt[i];
    }
    if (i == 0) g_rowptr[0] = 0;
}

// scatter: store SRC node id directly (avoids eid->src indirection in attention)
__global__ void k_scatter(const int* __restrict__ src, const int* __restrict__ dst, int e) {
    int i = blockIdx.x * blockDim.x + threadIdx.x;
    if (i < e) {
        int p = atomicAdd(&g_cursor[dst[i]], 1);
        g_esrc[p] = src[i];
    }
}

// ---------------- weight packing (both layers in one kernel) ----------------
__device__ __forceinline__ void pack_one(float* Wdst, float* bdst, int i, int K,
                                         const float* Wq, const float* bq,
                                         const float* Wk, const float* bk,
                                         const float* Wv, const float* bv,
                                         const float* Ws, const float* bs) {
    if (i < K * NC) {
        int k = i / NC, j = i % NC;
        float w;
        if (j < 128)      w = Wq[k * 128 + j];
        else if (j < 256) w = Wk[k * 128 + (j - 128)];
        else if (j < 384) w = Wv[k * 128 + (j - 256)];
        else              w = Ws[k * 32 + (j - 384)];
        Wdst[k * NC + j] = w;
    }
    if (i < NC) {
        float b;
        if (i < 128)      b = bq[i];
        else if (i < 256) b = bk[i - 128];
        else if (i < 384) b = bv[i - 256];
        else              b = bs[i - 384];
        bdst[i] = b;
    }
}

__global__ void k_pack_all(const float* Wq0, const float* bq0, const float* Wk0, const float* bk0,
                           const float* Wv0, const float* bv0, const float* Ws0, const float* bs0,
                           const float* Wq1, const float* bq1, const float* Wk1, const float* bk1,
                           const float* Wv1, const float* bv1, const float* Ws1, const float* bs1) {
    int i = blockIdx.x * blockDim.x + threadIdx.x;
    const int T0 = 128 * NC;
    if (i < T0)
        pack_one(g_Wcat0, g_bcat0, i, 128, Wq0, bq0, Wk0, bk0, Wv0, bv0, Ws0, bs0);
    else
        pack_one(g_Wcat1, g_bcat1, i - T0, 32, Wq1, bq1, Wk1, bk1, Wv1, bv1, Ws1, bs1);
}

// ---------------- TF32 tensor-core GEMM: C[M,416] = A[M,K] @ Wcat + bcat ----------------
// BM=128 BN=64 BK=32, 256 threads = 8 warps (4x2). Warp tile 32x32 via m16n8k8.
__device__ __forceinline__ uint32_t f2tf32(float x) {
    uint32_t r;
    asm("cvt.rna.tf32.f32 %0, %1;" : "=r"(r) : "f"(x));
    return r;
}

__device__ __forceinline__ void mma_tf32(float c[4], uint32_t a0, uint32_t a1, uint32_t a2,
                                         uint32_t a3, uint32_t b0, uint32_t b1) {
    asm volatile(
        "mma.sync.aligned.m16n8k8.row.col.f32.tf32.tf32.f32 "
        "{%0,%1,%2,%3}, {%4,%5,%6,%7}, {%8,%9}, {%0,%1,%2,%3};\n"
        : "+f"(c[0]), "+f"(c[1]), "+f"(c[2]), "+f"(c[3])
        : "r"(a0), "r"(a1), "r"(a2), "r"(a3), "r"(b0), "r"(b1));
}

__device__ __forceinline__ void store2(int row, int c, float v0, float v1) {
    if (c < 128) {
        *(float2*)(g_qs + (size_t)row * QS_STRIDE + c) = make_float2(v0, v1);
    } else if (c < 384) {
        *(float2*)(g_kv + (size_t)row * KV_STRIDE + (c - 128)) = make_float2(v0, v1);
    } else {
        *(float2*)(g_qs + (size_t)row * QS_STRIDE + 128 + (c - 384)) = make_float2(v0, v1);
    }
}

__global__ void __launch_bounds__(256) k_gemm(const float* __restrict__ A_ext, int layer,
                                              int M, int K) {
    __shared__ float As[128 * 36];   // stride 36 -> conflict-free fragment loads
    __shared__ float Bs[32 * 72];    // stride 72 -> conflict-free fragment loads
    const float* __restrict__ A = layer ? g_h : A_ext;
    const float* __restrict__ Wc = layer ? g_Wcat1 : g_Wcat0;
    const float* __restrict__ bc = layer ? g_bcat1 : g_bcat0;

    int m0 = blockIdx.x * 128;
    int n0 = blockIdx.y * 64;
    int tid = threadIdx.x;
    int wid = tid >> 5, lane = tid & 31;
    int wm = wid >> 1, wn = wid & 1;           // 4 x 2 warp grid
    int gid = lane >> 2, tig = lane & 3;       // mma group / thread-in-group

    float acc[2][4][4];
#pragma unroll
    for (int t = 0; t < 2; ++t)
#pragma unroll
        for (int nt = 0; nt < 4; ++nt)
#pragma unroll
            for (int j = 0; j < 4; ++j) acc[t][nt][j] = 0.f;

    for (int k0 = 0; k0 < K; k0 += 32) {
        // load A tile 128x32 (tf32-rounded)
#pragma unroll
        for (int t = 0; t < 4; ++t) {
            int idx = tid + t * 256;
            int r = idx >> 3;
            int c = (idx & 7) << 2;
            float4 v = make_float4(0.f, 0.f, 0.f, 0.f);
            int grow = m0 + r;
            if (grow < M) v = *(const float4*)(A + (size_t)grow * K + (k0 + c));
            float* p = &As[r * 36 + c];
            p[0] = __uint_as_float(f2tf32(v.x));
            p[1] = __uint_as_float(f2tf32(v.y));
            p[2] = __uint_as_float(f2tf32(v.z));
            p[3] = __uint_as_float(f2tf32(v.w));
        }
        // load B tile 32x64 (tf32-rounded)
#pragma unroll
        for (int t = 0; t < 2; ++t) {
            int idx = tid + t * 256;
            int r = idx >> 4;
            int c = (idx & 15) << 2;
            float4 v = make_float4(0.f, 0.f, 0.f, 0.f);
            int gcol = n0 + c;
            if (gcol < NC) v = *(const float4*)(Wc + (size_t)(k0 + r) * NC + gcol);
            float* p = &Bs[r * 72 + c];
            p[0] = __uint_as_float(f2tf32(v.x));
            p[1] = __uint_as_float(f2tf32(v.y));
            p[2] = __uint_as_float(f2tf32(v.z));
            p[3] = __uint_as_float(f2tf32(v.w));
        }
        __syncthreads();

#pragma unroll
        for (int kc = 0; kc < 4; ++kc) {
            int kk = kc * 8;
            uint32_t a[2][4];
#pragma unroll
            for (int t = 0; t < 2; ++t) {
                int rb = wm * 32 + t * 16;
                a[t][0] = __float_as_uint(As[(rb + gid) * 36 + kk + tig]);
                a[t][1] = __float_as_uint(As[(rb + gid + 8) * 36 + kk + tig]);
                a[t][2] = __float_as_uint(As[(rb + gid) * 36 + kk + tig + 4]);
                a[t][3] = __float_as_uint(As[(rb + gid + 8) * 36 + kk + tig + 4]);
            }
            uint32_t b[4][2];
#pragma unroll
            for (int nt = 0; nt < 4; ++nt) {
                int col = wn * 32 + nt * 8 + gid;
                b[nt][0] = __float_as_uint(Bs[(kk + tig) * 72 + col]);
                b[nt][1] = __float_as_uint(Bs[(kk + tig + 4) * 72 + col]);
            }
#pragma unroll
            for (int t = 0; t < 2; ++t)
#pragma unroll
                for (int nt = 0; nt < 4; ++nt)
                    mma_tf32(acc[t][nt], a[t][0], a[t][1], a[t][2], a[t][3],
                             b[nt][0], b[nt][1]);
        }
        __syncthreads();
    }

    // epilogue: bias + routed store
#pragma unroll
    for (int t = 0; t < 2; ++t) {
        int r0 = m0 + wm * 32 + t * 16 + gid;
#pragma unroll
        for (int nt = 0; nt < 4; ++nt) {
            int c = n0 + wn * 32 + nt * 8 + tig * 2;
            if (c >= NC) continue;
            float b0v = __ldg(bc + c), b1v = __ldg(bc + c + 1);
            if (r0 < M)      store2(r0,     c, acc[t][nt][0] + b0v, acc[t][nt][1] + b1v);
            if (r0 + 8 < M)  store2(r0 + 8, c, acc[t][nt][2] + b0v, acc[t][nt][3] + b1v);
        }
    }
}

// ---------------- attention: warp per destination node, online softmax ----------------
__global__ void k_attn(int n) {
    int gw = (blockIdx.x * blockDim.x + threadIdx.x) >> 5;
    if (gw >= n) return;
    int lane = threadIdx.x & 31;
    int g = lane >> 3, l = lane & 7;
    int off = g * 32 + l * 4;
    const float scale = 0.17677669529663687f;  // 1/sqrt(32)

    float4 q = *(const float4*)(g_qs + (size_t)gw * QS_STRIDE + off);
    float m = -1e30f, ssum = 0.f;
    float ax = 0.f, ay = 0.f, az = 0.f, aw = 0.f;

    int beg = g_rowptr[gw], end = g_rowptr[gw + 1];

    // 2-deep software pipeline: src prefetched 2 ahead, k/v 1 ahead
    float4 kc = make_float4(0, 0, 0, 0), vc = make_float4(0, 0, 0, 0);
    int sA = 0;
    if (beg < end) {
        int s0 = __ldg(g_esrc + beg);
        const float* kb = g_kv + (size_t)s0 * KV_STRIDE + off;
        kc = *(const float4*)kb;
        vc = *(const float4*)(kb + 128);
        if (beg + 1 < end) sA = __ldg(g_esrc + beg + 1);
    }

    for (int i = beg; i < end; ++i) {
        int sN = sA;
        if (i + 2 < end) sA = __ldg(g_esrc + i + 2);
        float4 kN = make_float4(0, 0, 0, 0), vN = kN;
        if (i + 1 < end) {
            const float* kb = g_kv + (size_t)sN * KV_STRIDE + off;
            kN = *(const float4*)kb;
            vN = *(const float4*)(kb + 128);
        }

        float d = q.x * kc.x + q.y * kc.y + q.z * kc.z + q.w * kc.w;
        d += __shfl_xor_sync(0xffffffffu, d, 1);
        d += __shfl_xor_sync(0xffffffffu, d, 2);
        d += __shfl_xor_sync(0xffffffffu, d, 4);
        float alpha = d * scale;
        if (alpha > m) {
            float sc = __expf(m - alpha);
            ssum = ssum * sc + 1.f;
            ax = ax * sc + vc.x;
            ay = ay * sc + vc.y;
            az = az * sc + vc.z;
            aw = aw * sc + vc.w;
            m = alpha;
        } else {
            float p = __expf(alpha - m);
            ssum += p;
            ax += p * vc.x;
            ay += p * vc.y;
            az += p * vc.z;
            aw += p * vc.w;
        }
        kc = kN; vc = vN;
    }
    float inv = (ssum > 0.f) ? (1.f / ssum) : 0.f;
    ax *= inv; ay *= inv; az *= inv; aw *= inv;

    ax += __shfl_xor_sync(0xffffffffu, ax, 8);
    ay += __shfl_xor_sync(0xffffffffu, ay, 8);
    az += __shfl_xor_sync(0xffffffffu, az, 8);
    aw += __shfl_xor_sync(0xffffffffu, aw, 8);
    ax += __shfl_xor_sync(0xffffffffu, ax, 16);
    ay += __shfl_xor_sync(0xffffffffu, ay, 16);
    az += __shfl_xor_sync(0xffffffffu, az, 16);
    aw += __shfl_xor_sync(0xffffffffu, aw, 16);

    if (lane < 8) {
        float4 sk = *(const float4*)(g_qs + (size_t)gw * QS_STRIDE + 128 + l * 4);
        float4 o;
        o.x = fmaxf(ax * 0.25f + sk.x, 0.f);
        o.y = fmaxf(ay * 0.25f + sk.y, 0.f);
        o.z = fmaxf(az * 0.25f + sk.z, 0.f);
        o.w = fmaxf(aw * 0.25f + sk.w, 0.f);
        *(float4*)(g_h + (size_t)gw * 32 + l * 4) = o;
    }
}

// ---------------- output projection: out[n,16] = h[n,32] @ Wout + bout ----------------
__global__ void __launch_bounds__(256) k_outproj(const float* __restrict__ Wout,
                                                 const float* __restrict__ bout,
                                                 float* __restrict__ out, int n) {
    __shared__ float Hs[128 * 32];
    __shared__ float Ws[512];
    __shared__ float Bs2[16];
    int node0 = blockIdx.x * 128;
    for (int i = threadIdx.x; i < 512; i += 256) Ws[i] = Wout[i];
    if (threadIdx.x < 16) Bs2[threadIdx.x] = bout[threadIdx.x];
    for (int i = threadIdx.x; i < 128 * 32; i += 256) {
        int r = node0 + (i >> 5);
        Hs[i] = (r < n) ? g_h[(size_t)node0 * 32 + i] : 0.f;
    }
    __syncthreads();
#pragma unroll
    for (int t = 0; t < 8; ++t) {
        int oi = threadIdx.x + t * 256;
        int ln = oi >> 4;
        int j = oi & 15;
        int node = node0 + ln;
        if (node >= n) continue;
        float acc = Bs2[j];
#pragma unroll
        for (int k = 0; k < 32; ++k) acc += Hs[ln * 32 + k] * Ws[k * 16 + j];
        out[(size_t)node * 16 + j] = acc;
    }
}

// ---------------- launch ----------------
extern "C" void kernel_launch(void* const* d_in, const int* in_sizes, int n_in,
                              void* d_out, int out_size) {
    const float* x = (const float*)d_in[0];
    const int*   ei = (const int*)d_in[1];
    int n = in_sizes[0] / 128;
    int e = in_sizes[1] / 2;
    const int* srcp = ei;
    const int* dstp = ei + e;

    int nb = (n + 255) / 256;
    int eb = (e + 255) / 256;
    int sblocks = (n + SCAN_B - 1) / SCAN_B;

    // CSR by destination (reused for both layers)
    k_zero_cnt<<<nb, 256>>>(n);
    k_hist<<<eb, 256>>>(dstp, e);
    k_scan1<<<sblocks, SCAN_B>>>(n);
    k_scan2<<<1, SCAN_B>>>(sblocks);
    k_scan3<<<sblocks, SCAN_B>>>(n);
    k_scatter<<<eb, 256>>>(srcp, dstp, e);

    // pack both layers' weights at once
    int pack_total = 128 * NC + 32 * NC;
    k_pack_all<<<(pack_total + 255) / 256, 256>>>(
        (const float*)d_in[2],  (const float*)d_in[3],
        (const float*)d_in[4],  (const float*)d_in[5],
        (const float*)d_in[6],  (const float*)d_in[7],
        (const float*)d_in[8],  (const float*)d_in[9],
        (const float*)d_in[10], (const float*)d_in[11],
        (const float*)d_in[12], (const float*)d_in[13],
        (const float*)d_in[14], (const float*)d_in[15],
        (const float*)d_in[16], (const float*)d_in[17]);

    dim3 gg((n + 127) / 128, (NC + 63) / 64);
    int attn_blocks = (n + 7) / 8;

    // layer 0
    k_gemm<<<gg, 256>>>(x, 0, n, 128);
    k_attn<<<attn_blocks, 256>>>(n);

    // layer 1
    k_gemm<<<gg, 256>>>(nullptr, 1, n, 32);
    k_attn<<<attn_blocks, 256>>>(n);

    // output projection
    k_outproj<<<(n + 127) / 128, 256>>>(
        (const float*)d_in[18], (const float*)d_in[19], (float*)d_out, n);
}

// round 4
// speedup vs baseline: 1.7953x; 1.0194x over previous
#include <cuda_runtime.h>
#include <math.h>
#include <stdint.h>

// ---------------- problem constants ----------------
#define NMAX 100000
#define EMAX 800000
#define NC 416            // packed GEMM output cols: Q(128) K(128) V(128) S(32)
#define QS_STRIDE 160     // q(128) + skip(32)
#define KV_STRIDE 256     // k(128) + v(128)
#define SCAN_B 1024

// ---------------- scratch (device globals; no allocs allowed) ----------------
__device__ __align__(16) float g_qs[(size_t)NMAX * QS_STRIDE];
__device__ __align__(16) float g_kv[(size_t)NMAX * KV_STRIDE];
__device__ __align__(16) float g_h[(size_t)NMAX * 32];
__device__ __align__(16) float g_Wcat0[128 * NC];
__device__ __align__(16) float g_Wcat1[32 * NC];
__device__ float g_bcat0[NC];
__device__ float g_bcat1[NC];
__device__ int   g_cnt[NMAX];
__device__ int   g_rowptr[NMAX + 1];
__device__ int   g_cursor[NMAX];
__device__ int   g_esrc[EMAX];     // src node id per CSR slot (pre-gathered)
__device__ int   g_bsums[1024];

// ---------------- CSR build ----------------
__global__ void k_zero_cnt(int n) {
    int i = blockIdx.x * blockDim.x + threadIdx.x;
    if (i < n) g_cnt[i] = 0;
}

__global__ void k_hist(const int* __restrict__ dst, int e) {
    int i = blockIdx.x * blockDim.x + threadIdx.x;
    if (i < e) atomicAdd(&g_cnt[dst[i]], 1);
}

__global__ void k_scan1(int n) {
    __shared__ int sm[SCAN_B];
    int i = blockIdx.x * SCAN_B + threadIdx.x;
    int v = (i < n) ? g_cnt[i] : 0;
    sm[threadIdx.x] = v;
    for (int off = 1; off < SCAN_B; off <<= 1) {
        __syncthreads();
        int t = (threadIdx.x >= off) ? sm[threadIdx.x - off] : 0;
        __syncthreads();
        sm[threadIdx.x] += t;
    }
    __syncthreads();
    if (i < n) g_rowptr[i + 1] = sm[threadIdx.x];
    if (threadIdx.x == SCAN_B - 1) g_bsums[blockIdx.x] = sm[SCAN_B - 1];
}

__global__ void k_scan2(int nb) {
    __shared__ int sm[SCAN_B];
    int v = (threadIdx.x < nb) ? g_bsums[threadIdx.x] : 0;
    sm[threadIdx.x] = v;
    for (int off = 1; off < SCAN_B; off <<= 1) {
        __syncthreads();
        int t = (threadIdx.x >= off) ? sm[threadIdx.x - off] : 0;
        __syncthreads();
        sm[threadIdx.x] += t;
    }
    __syncthreads();
    if (threadIdx.x < nb) g_bsums[threadIdx.x] = sm[threadIdx.x] - v; // exclusive
}

// scan3 also derives cursor[i] = rowptr[i+1] - cnt[i], and rowptr[0]=0.
__global__ void k_scan3(int n) {
    int i = blockIdx.x * SCAN_B + threadIdx.x;
    if (i < n) {
        int v = g_rowptr[i + 1] + g_bsums[blockIdx.x];
        g_rowptr[i + 1] = v;
        g_cursor[i] = v - g_cnt[i];
    }
    if (i == 0) g_rowptr[0] = 0;
}

__global__ void k_scatter(const int* __restrict__ src, const int* __restrict__ dst, int e) {
    int i = blockIdx.x * blockDim.x + threadIdx.x;
    if (i < e) {
        int p = atomicAdd(&g_cursor[dst[i]], 1);
        g_esrc[p] = src[i];
    }
}

// ---------------- weight packing: Wcat[K][416] row-major + bias ----------------
__device__ __forceinline__ void pack_one(float* Wdst, float* bdst, int i, int K,
                                         const float* Wq, const float* bq,
                                         const float* Wk, const float* bk,
                                         const float* Wv, const float* bv,
                                         const float* Ws, const float* bs) {
    if (i < K * NC) {
        int k = i / NC, j = i % NC;
        float w;
        if (j < 128)      w = Wq[k * 128 + j];
        else if (j < 256) w = Wk[k * 128 + (j - 128)];
        else if (j < 384) w = Wv[k * 128 + (j - 256)];
        else              w = Ws[k * 32 + (j - 384)];
        Wdst[k * NC + j] = w;
    }
    if (i < NC) {
        float b;
        if (i < 128)      b = bq[i];
        else if (i < 256) b = bk[i - 128];
        else if (i < 384) b = bv[i - 256];
        else              b = bs[i - 384];
        bdst[i] = b;
    }
}

__global__ void k_pack_all(const float* Wq0, const float* bq0, const float* Wk0, const float* bk0,
                           const float* Wv0, const float* bv0, const float* Ws0, const float* bs0,
                           const float* Wq1, const float* bq1, const float* Wk1, const float* bk1,
                           const float* Wv1, const float* bv1, const float* Ws1, const float* bs1) {
    int i = blockIdx.x * blockDim.x + threadIdx.x;
    const int T0 = 128 * NC;
    if (i < T0)
        pack_one(g_Wcat0, g_bcat0, i, 128, Wq0, bq0, Wk0, bk0, Wv0, bv0, Ws0, bs0);
    else
        pack_one(g_Wcat1, g_bcat1, i - T0, 32, Wq1, bq1, Wk1, bk1, Wv1, bv1, Ws1, bs1);
}

// ---------------- TF32 tensor-core GEMM with A-reuse across N-tiles ----------------
// One CTA owns 128 rows. A[128,K] loaded & tf32-converted ONCE into SMEM, then the
// 7 N-tiles (64 cols each, last 32) are processed in-place reloading only B.
__device__ __forceinline__ uint32_t f2tf32(float x) {
    uint32_t r;
    asm("cvt.rna.tf32.f32 %0, %1;" : "=r"(r) : "f"(x));
    return r;
}

__device__ __forceinline__ void mma_tf32(float c[4], uint32_t a0, uint32_t a1, uint32_t a2,
                                         uint32_t a3, uint32_t b0, uint32_t b1) {
    asm volatile(
        "mma.sync.aligned.m16n8k8.row.col.f32.tf32.tf32.f32 "
        "{%0,%1,%2,%3}, {%4,%5,%6,%7}, {%8,%9}, {%0,%1,%2,%3};\n"
        : "+f"(c[0]), "+f"(c[1]), "+f"(c[2]), "+f"(c[3])
        : "r"(a0), "r"(a1), "r"(a2), "r"(a3), "r"(b0), "r"(b1));
}

__device__ __forceinline__ void store2(int row, int c, float v0, float v1) {
    if (c < 128) {
        *(float2*)(g_qs + (size_t)row * QS_STRIDE + c) = make_float2(v0, v1);
    } else if (c < 384) {
        *(float2*)(g_kv + (size_t)row * KV_STRIDE + (c - 128)) = make_float2(v0, v1);
    } else {
        *(float2*)(g_qs + (size_t)row * QS_STRIDE + 128 + (c - 384)) = make_float2(v0, v1);
    }
}

template <int K>
__global__ void __launch_bounds__(256) k_gemm(const float* __restrict__ A_ext, int M) {
    extern __shared__ float smf[];
    float* biassm = smf;                       // NC floats (448 slot, padded)
    float* As = smf + 448;                     // 128 x (K+4)
    float* Bs = As + 128 * (K + 4);            // K x 68
    const bool L1 = (K == 32);
    const float* __restrict__ A = L1 ? g_h : A_ext;
    const float* __restrict__ Wc = L1 ? g_Wcat1 : g_Wcat0;
    const float* __restrict__ bc = L1 ? g_bcat1 : g_bcat0;

    int m0 = blockIdx.x * 128;
    int tid = threadIdx.x;
    int wid = tid >> 5, lane = tid & 31;
    int wm = wid >> 1, wn = wid & 1;           // 4 x 2 warp grid over 128x64
    int gid = lane >> 2, tig = lane & 3;       // mma group / thread-in-group

    for (int i = tid; i < NC; i += 256) biassm[i] = bc[i];

    // ---- load A once, tf32-converted ----
    constexpr int C4 = K / 4;                  // float4s per row
#pragma unroll
    for (int t = 0; t < (128 * C4) / 256; ++t) {
        int idx = tid + t * 256;
        int r = idx / C4;
        int c4 = idx % C4;
        float4 v = make_float4(0.f, 0.f, 0.f, 0.f);
        int gr = m0 + r;
        if (gr < M) v = *(const float4*)(A + (size_t)gr * K + c4 * 4);
        float4 o;
        o.x = __uint_as_float(f2tf32(v.x));
        o.y = __uint_as_float(f2tf32(v.y));
        o.z = __uint_as_float(f2tf32(v.z));
        o.w = __uint_as_float(f2tf32(v.w));
        *(float4*)&As[r * (K + 4) + c4 * 4] = o;
    }
    __syncthreads();

    // ---- N-tile loop ----
#pragma unroll 1
    for (int t = 0; t < 7; ++t) {
        int n0 = t * 64;
        // load B tile [K][64] (tf32-converted), stride 68
#pragma unroll
        for (int u = 0; u < (K * 16) / 256; ++u) {
            int idx = tid + u * 256;
            int r = idx >> 4;
            int c4 = (idx & 15) << 2;
            int gc = n0 + c4;
            float4 v = make_float4(0.f, 0.f, 0.f, 0.f);
            if (gc < NC) v = *(const float4*)(Wc + (size_t)r * NC + gc);
            float4 o;
            o.x = __uint_as_float(f2tf32(v.x));
            o.y = __uint_as_float(f2tf32(v.y));
            o.z = __uint_as_float(f2tf32(v.z));
            o.w = __uint_as_float(f2tf32(v.w));
            *(float4*)&Bs[r * 68 + c4] = o;
        }
        __syncthreads();

        float acc[2][4][4];
#pragma unroll
        for (int a = 0; a < 2; ++a)
#pragma unroll
            for (int nt = 0; nt < 4; ++nt)
#pragma unroll
                for (int j = 0; j < 4; ++j) acc[a][nt][j] = 0.f;

#pragma unroll
        for (int kc = 0; kc < K / 8; ++kc) {
            int kk = kc * 8;
            uint32_t a[2][4];
#pragma unroll
            for (int q = 0; q < 2; ++q) {
                int rb = wm * 32 + q * 16;
                a[q][0] = __float_as_uint(As[(rb + gid) * (K + 4) + kk + tig]);
                a[q][1] = __float_as_uint(As[(rb + gid + 8) * (K + 4) + kk + tig]);
                a[q][2] = __float_as_uint(As[(rb + gid) * (K + 4) + kk + tig + 4]);
                a[q][3] = __float_as_uint(As[(rb + gid + 8) * (K + 4) + kk + tig + 4]);
            }
            uint32_t b[4][2];
#pragma unroll
            for (int nt = 0; nt < 4; ++nt) {
                int col = wn * 32 + nt * 8 + gid;
                b[nt][0] = __float_as_uint(Bs[(kk + tig) * 68 + col]);
                b[nt][1] = __float_as_uint(Bs[(kk + tig + 4) * 68 + col]);
            }
#pragma unroll
            for (int q = 0; q < 2; ++q)
#pragma unroll
                for (int nt = 0; nt < 4; ++nt)
                    mma_tf32(acc[q][nt], a[q][0], a[q][1], a[q][2], a[q][3],
                             b[nt][0], b[nt][1]);
        }

        // epilogue for this tile
#pragma unroll
        for (int q = 0; q < 2; ++q) {
            int r0 = m0 + wm * 32 + q * 16 + gid;
#pragma unroll
            for (int nt = 0; nt < 4; ++nt) {
                int c = n0 + wn * 32 + nt * 8 + tig * 2;
                if (c >= NC) continue;
                float b0v = biassm[c], b1v = biassm[c + 1];
                if (r0 < M)      store2(r0,     c, acc[q][nt][0] + b0v, acc[q][nt][1] + b1v);
                if (r0 + 8 < M)  store2(r0 + 8, c, acc[q][nt][2] + b0v, acc[q][nt][3] + b1v);
            }
        }
        __syncthreads();   // Bs reused next tile
    }
}

// ---------------- attention: warp per destination node, online softmax ----------------
__global__ void k_attn(int n) {
    int gw = (blockIdx.x * blockDim.x + threadIdx.x) >> 5;
    if (gw >= n) return;
    int lane = threadIdx.x & 31;
    int g = lane >> 3, l = lane & 7;
    int off = g * 32 + l * 4;
    const float scale = 0.17677669529663687f;  // 1/sqrt(32)

    float4 q = *(const float4*)(g_qs + (size_t)gw * QS_STRIDE + off);
    float m = -1e30f, ssum = 0.f;
    float ax = 0.f, ay = 0.f, az = 0.f, aw = 0.f;

    int beg = g_rowptr[gw], end = g_rowptr[gw + 1];

    float4 kc = make_float4(0, 0, 0, 0), vc = make_float4(0, 0, 0, 0);
    int sA = 0;
    if (beg < end) {
        int s0 = __ldg(g_esrc + beg);
        const float* kb = g_kv + (size_t)s0 * KV_STRIDE + off;
        kc = *(const float4*)kb;
        vc = *(const float4*)(kb + 128);
        if (beg + 1 < end) sA = __ldg(g_esrc + beg + 1);
    }

    for (int i = beg; i < end; ++i) {
        int sN = sA;
        if (i + 2 < end) sA = __ldg(g_esrc + i + 2);
        float4 kN = make_float4(0, 0, 0, 0), vN = kN;
        if (i + 1 < end) {
            const float* kb = g_kv + (size_t)sN * KV_STRIDE + off;
            kN = *(const float4*)kb;
            vN = *(const float4*)(kb + 128);
        }

        float d = q.x * kc.x + q.y * kc.y + q.z * kc.z + q.w * kc.w;
        d += __shfl_xor_sync(0xffffffffu, d, 1);
        d += __shfl_xor_sync(0xffffffffu, d, 2);
        d += __shfl_xor_sync(0xffffffffu, d, 4);
        float alpha = d * scale;
        if (alpha > m) {
            float sc = __expf(m - alpha);
            ssum = ssum * sc + 1.f;
            ax = ax * sc + vc.x;
            ay = ay * sc + vc.y;
            az = az * sc + vc.z;
            aw = aw * sc + vc.w;
            m = alpha;
        } else {
            float p = __expf(alpha - m);
            ssum += p;
            ax += p * vc.x;
            ay += p * vc.y;
            az += p * vc.z;
            aw += p * vc.w;
        }
        kc = kN; vc = vN;
    }
    float inv = (ssum > 0.f) ? (1.f / ssum) : 0.f;
    ax *= inv; ay *= inv; az *= inv; aw *= inv;

    ax += __shfl_xor_sync(0xffffffffu, ax, 8);
    ay += __shfl_xor_sync(0xffffffffu, ay, 8);
    az += __shfl_xor_sync(0xffffffffu, az, 8);
    aw += __shfl_xor_sync(0xffffffffu, aw, 8);
    ax += __shfl_xor_sync(0xffffffffu, ax, 16);
    ay += __shfl_xor_sync(0xffffffffu, ay, 16);
    az += __shfl_xor_sync(0xffffffffu, az, 16);
    aw += __shfl_xor_sync(0xffffffffu, aw, 16);

    if (lane < 8) {
        float4 sk = *(const float4*)(g_qs + (size_t)gw * QS_STRIDE + 128 + l * 4);
        float4 o;
        o.x = fmaxf(ax * 0.25f + sk.x, 0.f);
        o.y = fmaxf(ay * 0.25f + sk.y, 0.f);
        o.z = fmaxf(az * 0.25f + sk.z, 0.f);
        o.w = fmaxf(aw * 0.25f + sk.w, 0.f);
        *(float4*)(g_h + (size_t)gw * 32 + l * 4) = o;
    }
}

// ---------------- output projection: out[n,16] = h[n,32] @ Wout + bout ----------------
__global__ void __launch_bounds__(256) k_outproj(const float* __restrict__ Wout,
                                                 const float* __restrict__ bout,
                                                 float* __restrict__ out, int n) {
    __shared__ float Hs[128 * 32];
    __shared__ float Ws[512];
    __shared__ float Bs2[16];
    int node0 = blockIdx.x * 128;
    for (int i = threadIdx.x; i < 512; i += 256) Ws[i] = Wout[i];
    if (threadIdx.x < 16) Bs2[threadIdx.x] = bout[threadIdx.x];
    for (int i = threadIdx.x; i < 128 * 32; i += 256) {
        int r = node0 + (i >> 5);
        Hs[i] = (r < n) ? g_h[(size_t)node0 * 32 + i] : 0.f;
    }
    __syncthreads();
#pragma unroll
    for (int t = 0; t < 8; ++t) {
        int oi = threadIdx.x + t * 256;
        int ln = oi >> 4;
        int j = oi & 15;
        int node = node0 + ln;
        if (node >= n) continue;
        float acc = Bs2[j];
#pragma unroll
        for (int k = 0; k < 32; ++k) acc += Hs[ln * 32 + k] * Ws[k * 16 + j];
        out[(size_t)node * 16 + j] = acc;
    }
}

// ---------------- launch ----------------
extern "C" void kernel_launch(void* const* d_in, const int* in_sizes, int n_in,
                              void* d_out, int out_size) {
    const float* x = (const float*)d_in[0];
    const int*   ei = (const int*)d_in[1];
    int n = in_sizes[0] / 128;
    int e = in_sizes[1] / 2;
    const int* srcp = ei;
    const int* dstp = ei + e;

    const int smem0 = (448 + 128 * 132 + 128 * 68) * 4;   // K=128: ~104 KB
    const int smem1 = (448 + 128 * 36 + 32 * 68) * 4;     // K=32:  ~29 KB
    cudaFuncSetAttribute(k_gemm<128>, cudaFuncAttributeMaxDynamicSharedMemorySize, smem0);
    cudaFuncSetAttribute(k_gemm<32>,  cudaFuncAttributeMaxDynamicSharedMemorySize, smem1);

    int nb = (n + 255) / 256;
    int eb = (e + 255) / 256;
    int sblocks = (n + SCAN_B - 1) / SCAN_B;
    int gemm_blocks = (n + 127) / 128;
    int attn_blocks = (n + 7) / 8;
    int pack_total = 128 * NC + 32 * NC;

    // launch order puts the L0 GEMM in the ncu capture slot (4th launch)
    k_pack_all<<<(pack_total + 255) / 256, 256>>>(
        (const float*)d_in[2],  (const float*)d_in[3],
        (const float*)d_in[4],  (const float*)d_in[5],
        (const float*)d_in[6],  (const float*)d_in[7],
        (const float*)d_in[8],  (const float*)d_in[9],
        (const float*)d_in[10], (const float*)d_in[11],
        (const float*)d_in[12], (const float*)d_in[13],
        (const float*)d_in[14], (const float*)d_in[15],
        (const float*)d_in[16], (const float*)d_in[17]);
    k_zero_cnt<<<nb, 256>>>(n);
    k_hist<<<eb, 256>>>(dstp, e);
    k_gemm<128><<<gemm_blocks, 256, smem0>>>(x, n);        // <- profiled slot
    k_scan1<<<sblocks, SCAN_B>>>(n);
    k_scan2<<<1, SCAN_B>>>(sblocks);
    k_scan3<<<sblocks, SCAN_B>>>(n);
    k_scatter<<<eb, 256>>>(srcp, dstp, e);
    k_attn<<<attn_blocks, 256>>>(n);
    k_gemm<32><<<gemm_blocks, 256, smem1>>>(nullptr, n);
    k_attn<<<attn_blocks, 256>>>(n);
    k_outproj<<<(n + 127) / 128, 256>>>(
        (const float*)d_in[18], (const float*)d_in[19], (float*)d_out, n);
}